// round 8
// baseline (speedup 1.0000x reference)
#include <cuda_runtime.h>

#define Bz 8
#define Hn 4
#define Ln 256
#define Dn 32

__global__ __launch_bounds__(256)
void taa_kernel(const float* __restrict__ Q, const float* __restrict__ K,
                const float* __restrict__ V, const float* __restrict__ tmK,
                const float* __restrict__ tmV, const float* __restrict__ amask,
                const unsigned char* __restrict__ pad,
                float* __restrict__ x_out, float* __restrict__ attn_out)
{
    __shared__ float sQ[2 * Dn];
    __shared__ float sE[2][Ln];        // energy, then attn (two q-rows)
    __shared__ float wmax[2][8];
    __shared__ float wsum[2][8];
    __shared__ float red[2][32 * Dn];  // 8 KB cross-group reduction

    const int bid = blockIdx.x;               // 4096 CTAs
    const int qi = bid & (Ln / 2 - 1);        // 0..127
    const int h  = (bid >> 7) & (Hn - 1);
    const int b  = bid >> 9;
    const int q0 = qi * 2;

    const int tid  = threadIdx.x;
    const int lane = tid & 31;
    const int wid  = tid >> 5;

    const int bh = b * Hn + h;
    const float* __restrict__ tmK0 = tmK + (((size_t)bh * Ln + q0) * Ln) * Dn;
    const float* __restrict__ tmK1 = tmK0 + (size_t)Ln * Dn;
    const float* __restrict__ tmV0 = tmV + (((size_t)bh * Ln + q0) * Ln) * Dn;
    const float* __restrict__ tmV1 = tmV0 + (size_t)Ln * Dn;
    const float* __restrict__ Kbh  = K + (size_t)bh * Ln * Dn;
    const float* __restrict__ Vbh  = V + (size_t)bh * Ln * Dn;

    if (tid < 2 * Dn) sQ[tid] = Q[((size_t)bh * Ln + q0) * Dn + tid];
    __syncthreads();

    const int k0 = tid >> 3;      // 0..31
    const int dq = tid & 7;       // 0..7
    const float4 qa = reinterpret_cast<const float4*>(sQ)[dq];
    const float4 qb = reinterpret_cast<const float4*>(sQ + Dn)[dq];

    // -------- Phase 1: two independent tmK streams, K shared --------
#pragma unroll
    for (int j = 0; j < 8; j++) {
        const int k = k0 + 32 * j;
        const float4 t0 = __ldcs(reinterpret_cast<const float4*>(tmK0 + (size_t)k * Dn) + dq);
        const float4 t1 = __ldcs(reinterpret_cast<const float4*>(tmK1 + (size_t)k * Dn) + dq);
        const float4 kv = __ldg (reinterpret_cast<const float4*>(Kbh  + (size_t)k * Dn) + dq);
        float p0 = (t0.x + kv.x) * qa.x + (t0.y + kv.y) * qa.y
                 + (t0.z + kv.z) * qa.z + (t0.w + kv.w) * qa.w;
        float p1 = (t1.x + kv.x) * qb.x + (t1.y + kv.y) * qb.y
                 + (t1.z + kv.z) * qb.z + (t1.w + kv.w) * qb.w;
        p0 += __shfl_down_sync(0xffffffffu, p0, 4, 8);
        p1 += __shfl_down_sync(0xffffffffu, p1, 4, 8);
        p0 += __shfl_down_sync(0xffffffffu, p0, 2, 8);
        p1 += __shfl_down_sync(0xffffffffu, p1, 2, 8);
        p0 += __shfl_down_sync(0xffffffffu, p0, 1, 8);
        p1 += __shfl_down_sync(0xffffffffu, p1, 1, 8);
        if (dq == 0) { sE[0][k] = p0; sE[1][k] = p1; }
    }
    __syncthreads();

    // -------- Softmax for both rows (shared barriers) --------
    const float inv_scale = 0.17677669529663689f;   // 1/sqrt(32)
    const bool padded = pad[b * Ln + tid];
    float e0 = sE[0][tid] * inv_scale + amask[q0 * Ln + tid];
    float e1 = sE[1][tid] * inv_scale + amask[(q0 + 1) * Ln + tid];
    if (padded) { e0 = -4294967295.0f; e1 = -4294967295.0f; }

    float m0 = e0, m1 = e1;
#pragma unroll
    for (int o = 16; o > 0; o >>= 1) {
        m0 = fmaxf(m0, __shfl_xor_sync(0xffffffffu, m0, o));
        m1 = fmaxf(m1, __shfl_xor_sync(0xffffffffu, m1, o));
    }
    if (lane == 0) { wmax[0][wid] = m0; wmax[1][wid] = m1; }
    __syncthreads();
    m0 = wmax[0][0]; m1 = wmax[1][0];
#pragma unroll
    for (int i = 1; i < 8; i++) { m0 = fmaxf(m0, wmax[0][i]); m1 = fmaxf(m1, wmax[1][i]); }

    const float ex0 = __expf(e0 - m0);
    const float ex1 = __expf(e1 - m1);
    float s0 = ex0, s1 = ex1;
#pragma unroll
    for (int o = 16; o > 0; o >>= 1) {
        s0 += __shfl_xor_sync(0xffffffffu, s0, o);
        s1 += __shfl_xor_sync(0xffffffffu, s1, o);
    }
    if (lane == 0) { wsum[0][wid] = s0; wsum[1][wid] = s1; }
    __syncthreads();
    s0 = wsum[0][0]; s1 = wsum[1][0];
#pragma unroll
    for (int i = 1; i < 8; i++) { s0 += wsum[0][i]; s1 += wsum[1][i]; }

    const float a0 = ex0 * __frcp_rn(s0);
    const float a1 = ex1 * __frcp_rn(s1);
    sE[0][tid] = a0;                   // thread t sole prior reader of sE[*][t]
    sE[1][tid] = a1;
    float* attn_base = attn_out + ((size_t)bh * Ln + q0) * Ln;
    __stcs(&attn_base[tid], a0);       // 8 warps share the store work
    __stcs(&attn_base[Ln + tid], a1);
    __syncthreads();

    // -------- Phase 2: two tmV streams, V shared --------
    float4 acc0 = make_float4(0.f, 0.f, 0.f, 0.f);
    float4 acc1 = make_float4(0.f, 0.f, 0.f, 0.f);
#pragma unroll
    for (int j = 0; j < 8; j++) {
        const int k = k0 + 32 * j;
        const float av0 = sE[0][k];
        const float av1 = sE[1][k];
        const float4 t0 = __ldcs(reinterpret_cast<const float4*>(tmV0 + (size_t)k * Dn) + dq);
        const float4 t1 = __ldcs(reinterpret_cast<const float4*>(tmV1 + (size_t)k * Dn) + dq);
        const float4 vv = __ldg (reinterpret_cast<const float4*>(Vbh  + (size_t)k * Dn) + dq);
        acc0.x += av0 * (t0.x + vv.x);  acc1.x += av1 * (t1.x + vv.x);
        acc0.y += av0 * (t0.y + vv.y);  acc1.y += av1 * (t1.y + vv.y);
        acc0.z += av0 * (t0.z + vv.z);  acc1.z += av1 * (t1.z + vv.z);
        acc0.w += av0 * (t0.w + vv.w);  acc1.w += av1 * (t1.w + vv.w);
    }
    reinterpret_cast<float4*>(red[0] + k0 * Dn)[dq] = acc0;
    reinterpret_cast<float4*>(red[1] + k0 * Dn)[dq] = acc1;
    __syncthreads();

    if (tid < 2 * Dn) {
        const int r = tid >> 5;        // row 0/1
        const int d = tid & 31;
        float xs = 0.f;
#pragma unroll
        for (int g = 0; g < 32; g++) xs += red[r][g * Dn + d];
        __stcs(&x_out[((size_t)bh * Ln + q0 + r) * Dn + d], xs);
    }
}

extern "C" void kernel_launch(void* const* d_in, const int* in_sizes, int n_in,
                              void* d_out, int out_size)
{
    const float* Q    = (const float*)d_in[0];
    const float* K    = (const float*)d_in[1];
    const float* V    = (const float*)d_in[2];
    const float* tmK  = (const float*)d_in[3];
    const float* tmV  = (const float*)d_in[4];
    const float* mask = (const float*)d_in[5];
    const unsigned char* pad = (const unsigned char*)d_in[6];

    float* out  = (float*)d_out;
    float* x    = out;                                // [B,H,L,D]
    float* attn = out + (size_t)Bz * Hn * Ln * Dn;    // [B,H,L,L]

    taa_kernel<<<Bz * Hn * Ln / 2, 256>>>(Q, K, V, tmK, tmV, mask, pad, x, attn);
}

// round 9
// speedup vs baseline: 1.0032x; 1.0032x over previous
#include <cuda_runtime.h>

#define Bz 8
#define Hn 4
#define Ln 256
#define Dn 32

__global__ __launch_bounds__(256)
void taa_kernel(const float* __restrict__ Q, const float* __restrict__ K,
                const float* __restrict__ V, const float* __restrict__ tmK,
                const float* __restrict__ tmV, const float* __restrict__ amask,
                const unsigned char* __restrict__ pad,
                float* __restrict__ x_out, float* __restrict__ attn_out)
{
    __shared__ float sQ[Dn];
    __shared__ float sE[Ln];          // energy, then attn
    __shared__ float wmax[8];
    __shared__ float wsum[8];
    __shared__ float red[32 * Dn];    // 32 k0-groups x 32 d

    const int bid = blockIdx.x;
    const int q = bid & (Ln - 1);
    const int h = (bid >> 8) & (Hn - 1);
    const int b = bid >> 10;

    const int tid  = threadIdx.x;
    const int lane = tid & 31;
    const int wid  = tid >> 5;

    const int bh = b * Hn + h;
    const float* __restrict__ Qrow = Q   + ((size_t)bh * Ln + q) * Dn;
    const float* __restrict__ tmKq = tmK + (((size_t)bh * Ln + q) * Ln) * Dn;
    const float* __restrict__ tmVq = tmV + (((size_t)bh * Ln + q) * Ln) * Dn;
    const float* __restrict__ Kbh  = K + (size_t)bh * Ln * Dn;
    const float* __restrict__ Vbh  = V + (size_t)bh * Ln * Dn;

    if (tid < Dn) sQ[tid] = Qrow[tid];
    __syncthreads();

    const int k0 = tid >> 3;      // 0..31
    const int dq = tid & 7;       // 0..7 (float4 index within D=32)
    const float4 q4 = reinterpret_cast<const float4*>(sQ)[dq];

    // ---------------- Phase 1: energy[k] = (tmK[k,:]+K[k,:]) . Q ----------------
#pragma unroll
    for (int j = 0; j < 8; j++) {
        const int k = k0 + 32 * j;
        const float4 tk = __ldcs(reinterpret_cast<const float4*>(tmKq + (size_t)k * Dn) + dq);
        const float4 kv = __ldg (reinterpret_cast<const float4*>(Kbh  + (size_t)k * Dn) + dq);
        float p = (tk.x + kv.x) * q4.x + (tk.y + kv.y) * q4.y
                + (tk.z + kv.z) * q4.z + (tk.w + kv.w) * q4.w;
        p += __shfl_down_sync(0xffffffffu, p, 4, 8);
        p += __shfl_down_sync(0xffffffffu, p, 2, 8);
        p += __shfl_down_sync(0xffffffffu, p, 1, 8);
        if (dq == 0) sE[k] = p;
    }
    __syncthreads();

    // ---------------- Softmax over k (row of 256) ----------------
    const float inv_scale = 0.17677669529663689f;   // 1/sqrt(32)
    float e = sE[tid] * inv_scale + amask[q * Ln + tid];
    if (pad[b * Ln + tid]) e = -4294967295.0f;      // -2^32 + 1

    float m = e;
#pragma unroll
    for (int o = 16; o > 0; o >>= 1) m = fmaxf(m, __shfl_xor_sync(0xffffffffu, m, o));
    if (lane == 0) wmax[wid] = m;
    __syncthreads();
    m = wmax[0];
#pragma unroll
    for (int i = 1; i < 8; i++) m = fmaxf(m, wmax[i]);

    const float ex = __expf(e - m);
    float s = ex;
#pragma unroll
    for (int o = 16; o > 0; o >>= 1) s += __shfl_xor_sync(0xffffffffu, s, o);
    if (lane == 0) wsum[wid] = s;
    __syncthreads();
    s = wsum[0];
#pragma unroll
    for (int i = 1; i < 8; i++) s += wsum[i];

    const float a = ex * __frcp_rn(s);
    __syncthreads();               // phase-1 sE reads complete before overwrite
    sE[tid] = a;
    __stcs(&attn_out[((size_t)bh * Ln + q) * Ln + tid], a);
    __syncthreads();

    // ---------------- Phase 2: x[d] = sum_k attn[k]*(tmV[k,d]+V[k,d]) ----------------
    float4 acc = make_float4(0.f, 0.f, 0.f, 0.f);
#pragma unroll
    for (int j = 0; j < 8; j++) {
        const int k = k0 + 32 * j;
        const float av = sE[k];
        const float4 tv = __ldcs(reinterpret_cast<const float4*>(tmVq + (size_t)k * Dn) + dq);
        const float4 vv = __ldg (reinterpret_cast<const float4*>(Vbh  + (size_t)k * Dn) + dq);
        acc.x += av * (tv.x + vv.x);
        acc.y += av * (tv.y + vv.y);
        acc.z += av * (tv.z + vv.z);
        acc.w += av * (tv.w + vv.w);
    }
    reinterpret_cast<float4*>(red + k0 * Dn)[dq] = acc;
    __syncthreads();

    if (tid < Dn) {
        float xs = 0.f;
#pragma unroll
        for (int g = 0; g < 32; g++) xs += red[g * Dn + tid];
        __stcs(&x_out[((size_t)bh * Ln + q) * Dn + tid], xs);
    }
}

extern "C" void kernel_launch(void* const* d_in, const int* in_sizes, int n_in,
                              void* d_out, int out_size)
{
    const float* Q    = (const float*)d_in[0];
    const float* K    = (const float*)d_in[1];
    const float* V    = (const float*)d_in[2];
    const float* tmK  = (const float*)d_in[3];
    const float* tmV  = (const float*)d_in[4];
    const float* mask = (const float*)d_in[5];
    const unsigned char* pad = (const unsigned char*)d_in[6];

    float* out  = (float*)d_out;
    float* x    = out;                                // [B,H,L,D]
    float* attn = out + (size_t)Bz * Hn * Ln * Dn;    // [B,H,L,L]

    taa_kernel<<<Bz * Hn * Ln, 256>>>(Q, K, V, tmK, tmV, mask, pad, x, attn);
}